// round 1
// baseline (speedup 1.0000x reference)
#include <cuda_runtime.h>
#include <cuda_bf16.h>

#define NB 64
#define NT 512
#define ND 1024

// scratch: packed (chain_pos | role<<16) per (b,t). Static device global — no allocation.
__device__ int g_packed[NB * NT];

// ---------------------------------------------------------------------------
// Kernel A: per-batch-row prefix scans (cumsum + cummax) -> chain_pos, role
// One block per batch row, 512 threads (one per t).
// ---------------------------------------------------------------------------
__global__ void gpe_scan_kernel(const int* __restrict__ input_ids,
                                const int* __restrict__ rel_ids) {
    __shared__ int s[NT];
    const int b = blockIdx.x;
    const int t = threadIdx.x;

    const int rel = rel_ids[b * NT + t];
    const int id  = input_ids[b * NT + t];
    const int inc = (rel > 0) ? 1 : 0;

    // inclusive cumsum of inc
    s[t] = inc;
    __syncthreads();
#pragma unroll
    for (int off = 1; off < NT; off <<= 1) {
        int v = (t >= off) ? s[t - off] : 0;
        __syncthreads();
        s[t] += v;
        __syncthreads();
    }
    const int c = s[t] - inc;  // exclusive cumsum = count of rel>0 before t

    const int prev_rel = (t > 0) ? rel_ids[b * NT + t - 1] : 0;
    const int reset = (rel == 0 && prev_rel > 0) ? 1 : 0;

    __syncthreads();
    // inclusive cummax of (reset ? c : 0)
    s[t] = reset ? c : 0;
    __syncthreads();
#pragma unroll
    for (int off = 1; off < NT; off <<= 1) {
        int v = (t >= off) ? s[t - off] : 0;
        __syncthreads();
        s[t] = max(s[t], v);
        __syncthreads();
    }
    const int baseline = s[t];
    const int cp = c - baseline;

    // role: 3 for input_ids<=4, else 2 if rel==0, else 0
    const int role = (id <= 4) ? 3 : ((rel == 0) ? 2 : 0);

    g_packed[b * NT + t] = cp | (role << 16);
}

// ---------------------------------------------------------------------------
// Kernel B: embedding sum. One block per t (512 blocks), 256 threads,
// each thread owns one float4 column chunk. Base (seq + 0.3*depth0) and the
// three reachable role rows (pre-scaled 0.2x) live in registers; the inner
// loop over all 64 batches only reads the chain row (L2-resident, 4 MiB
// table) and stores the output row.
// ---------------------------------------------------------------------------
__global__ __launch_bounds__(256) void gpe_emb_kernel(
    const float* __restrict__ seq_table,
    const float* __restrict__ chain_table,
    const float* __restrict__ depth_table,
    const float* __restrict__ role_table,
    float* __restrict__ out) {

    const int t = blockIdx.x;
    const int tid = threadIdx.x;
    const int d = tid * 4;

    __shared__ int spk[NB];
    if (tid < NB) spk[tid] = g_packed[tid * NT + t];

    const float4 s4 = *(const float4*)(seq_table + (size_t)t * ND + d);
    const float4 dp = *(const float4*)(depth_table + d);  // depth row 0 always
    float4 base;
    base.x = s4.x + 0.3f * dp.x;
    base.y = s4.y + 0.3f * dp.y;
    base.z = s4.z + 0.3f * dp.z;
    base.w = s4.w + 0.3f * dp.w;

    // roles used: 0, 2, 3 (1 unreachable). Pre-scale by 0.2 and add to base later.
    float4 r0 = *(const float4*)(role_table + 0 * ND + d);
    float4 r2 = *(const float4*)(role_table + 2 * ND + d);
    float4 r3 = *(const float4*)(role_table + 3 * ND + d);
    r0.x *= 0.2f; r0.y *= 0.2f; r0.z *= 0.2f; r0.w *= 0.2f;
    r2.x *= 0.2f; r2.y *= 0.2f; r2.z *= 0.2f; r2.w *= 0.2f;
    r3.x *= 0.2f; r3.y *= 0.2f; r3.z *= 0.2f; r3.w *= 0.2f;

    __syncthreads();

#pragma unroll 4
    for (int b = 0; b < NB; b++) {
        const int pk = spk[b];
        const int cp = pk & 0xFFFF;
        const int role = pk >> 16;

        const float4 c4 = *(const float4*)(chain_table + (size_t)cp * ND + d);
        const float4 r4 = (role == 3) ? r3 : ((role == 2) ? r2 : r0);

        float4 o;
        o.x = base.x + 0.5f * c4.x + r4.x;
        o.y = base.y + 0.5f * c4.y + r4.y;
        o.z = base.z + 0.5f * c4.z + r4.z;
        o.w = base.w + 0.5f * c4.w + r4.w;

        *(float4*)(out + ((size_t)b * NT + t) * ND + d) = o;
    }
}

extern "C" void kernel_launch(void* const* d_in, const int* in_sizes, int n_in,
                              void* d_out, int out_size) {
    const int* input_ids   = (const int*)d_in[0];
    const int* rel_ids     = (const int*)d_in[1];
    const float* seq_table = (const float*)d_in[2];
    const float* chain_tab = (const float*)d_in[3];
    const float* depth_tab = (const float*)d_in[4];
    const float* role_tab  = (const float*)d_in[5];
    float* out = (float*)d_out;

    gpe_scan_kernel<<<NB, NT>>>(input_ids, rel_ids);
    gpe_emb_kernel<<<NT, 256>>>(seq_table, chain_tab, depth_tab, role_tab, out);
}

// round 2
// speedup vs baseline: 1.2551x; 1.2551x over previous
#include <cuda_runtime.h>
#include <cuda_bf16.h>

#define NB 64
#define NT 512
#define ND 1024
#define BPB 16  // batches per block in kernel B

// scratch: packed (chain_pos | role<<16) per (b,t). Static device global.
__device__ int g_packed[NB * NT];

// ---------------------------------------------------------------------------
// Kernel A: per-batch-row prefix scans (cumsum + cummax) via warp shuffles.
// One block per batch row, 512 threads (16 warps).
// ---------------------------------------------------------------------------
__global__ __launch_bounds__(512) void gpe_scan_kernel(
    const int* __restrict__ input_ids,
    const int* __restrict__ rel_ids) {
    __shared__ int wred[16];

    const int b = blockIdx.x;
    const int t = threadIdx.x;
    const int lane = t & 31;
    const int w = t >> 5;

    const int rel = rel_ids[b * NT + t];
    const int id  = input_ids[b * NT + t];
    const int inc = (rel > 0) ? 1 : 0;

    // ---- inclusive warp cumsum of inc ----
    int x = inc;
#pragma unroll
    for (int off = 1; off < 32; off <<= 1) {
        int v = __shfl_up_sync(0xFFFFFFFFu, x, off);
        if (lane >= off) x += v;
    }
    if (lane == 31) wred[w] = x;
    __syncthreads();
    if (w == 0) {
        int y = (lane < 16) ? wred[lane] : 0;
#pragma unroll
        for (int off = 1; off < 16; off <<= 1) {
            int v = __shfl_up_sync(0xFFFFFFFFu, y, off);
            if (lane >= off) y += v;
        }
        if (lane < 16) wred[lane] = y;
    }
    __syncthreads();
    const int c = x - inc + ((w > 0) ? wred[w - 1] : 0);  // exclusive cumsum

    const int prev_rel = (t > 0) ? rel_ids[b * NT + t - 1] : 0;
    const int reset = (rel == 0 && prev_rel > 0);
    __syncthreads();  // wred reuse

    // ---- inclusive warp cummax of (reset ? c : 0) ----
    int m = reset ? c : 0;
#pragma unroll
    for (int off = 1; off < 32; off <<= 1) {
        int v = __shfl_up_sync(0xFFFFFFFFu, m, off);
        if (lane >= off) m = max(m, v);
    }
    if (lane == 31) wred[w] = m;
    __syncthreads();
    if (w == 0) {
        int y = (lane < 16) ? wred[lane] : 0;
#pragma unroll
        for (int off = 1; off < 16; off <<= 1) {
            int v = __shfl_up_sync(0xFFFFFFFFu, y, off);
            if (lane >= off) y = max(y, v);
        }
        if (lane < 16) wred[lane] = y;
    }
    __syncthreads();
    const int baseline = max(m, (w > 0) ? wred[w - 1] : 0);
    const int cp = c - baseline;

    const int role = (id <= 4) ? 3 : ((rel == 0) ? 2 : 0);
    g_packed[b * NT + t] = cp | (role << 16);
}

// ---------------------------------------------------------------------------
// streaming (evict-first) float4 store — keeps the 134MB output stream from
// thrashing the L2-resident chain table.
// ---------------------------------------------------------------------------
__device__ __forceinline__ void stcs4(float4* p, float4 v) {
    asm volatile("st.global.cs.v4.f32 [%0], {%1,%2,%3,%4};"
                 :: "l"(p), "f"(v.x), "f"(v.y), "f"(v.z), "f"(v.w) : "memory");
}

// ---------------------------------------------------------------------------
// Kernel B: embedding sum. Grid (NT, NB/BPB) = (512, 4), 256 threads/block,
// each thread owns one float4 column. Base (seq + 0.3*depth0) and the three
// reachable role rows (pre-scaled) live in registers; inner loop over BPB
// batches reads only the chain row and streams the output.
// ---------------------------------------------------------------------------
__global__ __launch_bounds__(256) void gpe_emb_kernel(
    const float* __restrict__ seq_table,
    const float* __restrict__ chain_table,
    const float* __restrict__ depth_table,
    const float* __restrict__ role_table,
    float* __restrict__ out) {

    const int t = blockIdx.x;
    const int b0 = blockIdx.y * BPB;
    const int tid = threadIdx.x;
    const int d = tid * 4;

    __shared__ int spk[BPB];
    if (tid < BPB) spk[tid] = g_packed[(b0 + tid) * NT + t];

    const float4 s4 = *(const float4*)(seq_table + (size_t)t * ND + d);
    const float4 dp = *(const float4*)(depth_table + d);  // depth row 0 always
    float4 base;
    base.x = s4.x + 0.3f * dp.x;
    base.y = s4.y + 0.3f * dp.y;
    base.z = s4.z + 0.3f * dp.z;
    base.w = s4.w + 0.3f * dp.w;

    float4 r0 = *(const float4*)(role_table + 0 * ND + d);
    float4 r2 = *(const float4*)(role_table + 2 * ND + d);
    float4 r3 = *(const float4*)(role_table + 3 * ND + d);
    r0.x *= 0.2f; r0.y *= 0.2f; r0.z *= 0.2f; r0.w *= 0.2f;
    r2.x *= 0.2f; r2.y *= 0.2f; r2.z *= 0.2f; r2.w *= 0.2f;
    r3.x *= 0.2f; r3.y *= 0.2f; r3.z *= 0.2f; r3.w *= 0.2f;

    __syncthreads();

#pragma unroll 8
    for (int i = 0; i < BPB; i++) {
        const int pk = spk[i];
        const int cp = pk & 0xFFFF;
        const int role = pk >> 16;

        const float4 c4 = *(const float4*)(chain_table + (size_t)cp * ND + d);
        const float4 r4 = (role == 3) ? r3 : ((role == 2) ? r2 : r0);

        float4 o;
        o.x = base.x + 0.5f * c4.x + r4.x;
        o.y = base.y + 0.5f * c4.y + r4.y;
        o.z = base.z + 0.5f * c4.z + r4.z;
        o.w = base.w + 0.5f * c4.w + r4.w;

        stcs4((float4*)(out + ((size_t)(b0 + i) * NT + t) * ND + d), o);
    }
}

extern "C" void kernel_launch(void* const* d_in, const int* in_sizes, int n_in,
                              void* d_out, int out_size) {
    const int* input_ids   = (const int*)d_in[0];
    const int* rel_ids     = (const int*)d_in[1];
    const float* seq_table = (const float*)d_in[2];
    const float* chain_tab = (const float*)d_in[3];
    const float* depth_tab = (const float*)d_in[4];
    const float* role_tab  = (const float*)d_in[5];
    float* out = (float*)d_out;

    gpe_scan_kernel<<<NB, NT>>>(input_ids, rel_ids);
    dim3 grid(NT, NB / BPB);
    gpe_emb_kernel<<<grid, 256>>>(seq_table, chain_tab, depth_tab, role_tab, out);
}